// round 1
// baseline (speedup 1.0000x reference)
#include <cuda_runtime.h>

// ---------------------------------------------------------------------------
// KANCouplingNet: 3 KAN layers (12->64->64->24), N = 32*64*64 = 131072 rows.
// Each layer = dense GEMM over per-input 9-feature vectors
//   f = [silu(x), B0(x)..B7(x)],  W[i][g][o] folded from (sb, coef*ss).
// fp32 with packed fma.rn.f32x2 accumulation.
// ---------------------------------------------------------------------------

#define MAXN (32 * 64 * 64)

__device__ float g_h1[64 * MAXN];
__device__ float g_h2[64 * MAXN];
__device__ float g_W0[12 * 9 * 64];
__device__ float g_W1[64 * 9 * 64];
__device__ float g_W2[64 * 9 * 24];

using ull = unsigned long long;

__device__ __forceinline__ ull pack2(float lo, float hi) {
    ull r;
    asm("mov.b64 %0, {%1,%2};" : "=l"(r) : "f"(lo), "f"(hi));
    return r;
}
__device__ __forceinline__ void fma2(ull& d, ull a, ull b) {
    asm("fma.rn.f32x2 %0, %1, %2, %0;" : "+l"(d) : "l"(a), "l"(b));
}
__device__ __forceinline__ void unpack2(ull v, float& lo, float& hi) {
    asm("mov.b64 {%0,%1}, %2;" : "=f"(lo), "=f"(hi) : "l"(v));
}

// Windowed Cox-de Boor (degree 3, 8 basis fns, 12 knots). Matches the
// reference recursion exactly (same knot values, same denominators as
// 1/(t[j+d]-t[j]) precomputed). dst[0]=silu(v), dst[1+j]=B_j(v).
__device__ __forceinline__ void kan_features(float v, const float* ts,
                                             const float* r1, const float* r2,
                                             const float* r3, float* dst) {
    dst[0] = v / (1.0f + __expf(-v));
#pragma unroll
    for (int j = 0; j < 8; j++) dst[1 + j] = 0.0f;

    if (!(v >= ts[0] && v < ts[11])) return;  // all basis zero outside domain

    int m = 0;  // interval: t[m] <= v < t[m+1]
#pragma unroll
    for (int j = 1; j < 11; j++)
        if (v >= ts[j]) m = j;

    // degree 1 (nonzero window: indices m-1..m)
    float a0 = 0.0f, a1 = 0.0f;
    if (m >= 1) a0 = (ts[m + 1] - v) * r1[m];      // index m-1
    if (m <= 9) a1 = (v - ts[m]) * r1[m];          // index m

    // degree 2 (indices m-2..m)
    float b0 = 0.0f, b1 = 0.0f, b2 = 0.0f;
    if (m >= 2) b0 = (ts[m + 1] - v) * r2[m - 1] * a0;                      // m-2
    if (m >= 1 && m <= 9)
        b1 = (v - ts[m - 1]) * r2[m - 1] * a0 + (ts[m + 2] - v) * r2[m] * a1;  // m-1
    if (m <= 8) b2 = (v - ts[m]) * r2[m] * a1;                              // m

    // degree 3 (indices m-3..m)
    float c0 = 0.0f, c1 = 0.0f, c2 = 0.0f, c3 = 0.0f;
    if (m >= 3) c0 = (ts[m + 1] - v) * r3[m - 2] * b0;                      // m-3
    if (m >= 2 && m <= 9)
        c1 = (v - ts[m - 2]) * r3[m - 2] * b0 + (ts[m + 2] - v) * r3[m - 1] * b1;  // m-2
    if (m >= 1 && m <= 8)
        c2 = (v - ts[m - 1]) * r3[m - 1] * b1 + (ts[m + 3] - v) * r3[m] * b2;      // m-1
    if (m <= 7) c3 = (v - ts[m]) * r3[m] * b2;                              // m

    int j;
    j = m - 3; if (j >= 0 && j <= 7) dst[1 + j] = c0;
    j = m - 2; if (j >= 0 && j <= 7) dst[1 + j] = c1;
    j = m - 1; if (j >= 0 && j <= 7) dst[1 + j] = c2;
    j = m;     if (j >= 0 && j <= 7) dst[1 + j] = c3;
}

// Fold W[i][g9][o]: g9==0 -> sb[i][o]; g9==1+g -> coef[i][o][g]*ss[i][o]
__global__ void fold_kernel(const float* __restrict__ coef,
                            const float* __restrict__ sb,
                            const float* __restrict__ ss,
                            float* __restrict__ W, int IN, int OUT) {
    int idx = blockIdx.x * blockDim.x + threadIdx.x;
    int total = IN * 9 * OUT;
    if (idx >= total) return;
    int o = idx % OUT;
    int g9 = (idx / OUT) % 9;
    int i = idx / (9 * OUT);
    float v;
    if (g9 == 0)
        v = sb[i * OUT + o];
    else
        v = coef[(i * OUT + o) * 8 + (g9 - 1)] * ss[i * OUT + o];
    W[idx] = v;
}

// One KAN layer. Block: 256 threads = 8 warps; warp og owns outputs
// [og*O_PER, (og+1)*O_PER); each thread handles 4 rows (rr*32 + lane),
// block handles 128 rows. Features staged in shared per 4-input chunk.
template <int IN, int OUT, int O_PER, bool IN_NCHW, bool OUT_NCHW>
__global__ void __launch_bounds__(256) kan_layer(
    const float* __restrict__ hin, const float* __restrict__ grid,
    const float* __restrict__ W, float* __restrict__ hout, int N) {
    constexpr int CHUNK = 4;
    constexpr int NP = O_PER / 2;
    constexpr bool ODD = (O_PER & 1) != 0;

    __shared__ float ts[12], r1s[11], r2s[10], r3s[9];
    __shared__ __align__(16) float Ws[CHUNK * 9 * OUT];
    __shared__ float Fs[CHUNK * 128 * 9];

    const int tid = threadIdx.x;
    const int row0 = blockIdx.x * 128;
    const int og = tid >> 5;
    const int lane = tid & 31;

    if (tid < 12) ts[tid] = grid[tid];
    if (tid < 11) r1s[tid] = 1.0f / (grid[tid + 1] - grid[tid]);
    if (tid < 10) r2s[tid] = 1.0f / (grid[tid + 2] - grid[tid]);
    if (tid < 9)  r3s[tid] = 1.0f / (grid[tid + 3] - grid[tid]);

    ull acc2[4][NP > 0 ? NP : 1];
    float accs[4];
#pragma unroll
    for (int r = 0; r < 4; r++) {
        accs[r] = 0.0f;
#pragma unroll
        for (int p = 0; p < NP; p++) acc2[r][p] = 0ULL;
    }

    for (int i0 = 0; i0 < IN; i0 += CHUNK) {
        __syncthreads();
        // stage weight chunk [CHUNK][9][OUT]
        for (int t = tid; t < CHUNK * 9 * OUT; t += 256)
            Ws[t] = W[i0 * 9 * OUT + t];
        // stage features: CHUNK inputs x 128 rows
        for (int t = tid; t < CHUNK * 128; t += 256) {
            int ci = t >> 7;
            int r = t & 127;
            int row = row0 + r;
            int idx;
            if (IN_NCHW)
                idx = (((row >> 12) * IN + (i0 + ci)) << 12) + (row & 4095);
            else
                idx = (i0 + ci) * N + row;
            kan_features(hin[idx], ts, r1s, r2s, r3s, &Fs[(ci * 128 + r) * 9]);
        }
        __syncthreads();

        for (int ci = 0; ci < CHUNK; ci++) {
#pragma unroll
            for (int g = 0; g < 9; g++) {
                const int wbase = (ci * 9 + g) * OUT + og * O_PER;
                ull w[NP > 0 ? NP : 1];
                float wlast = 0.0f;
                if (!ODD) {
                    const ull* wp = reinterpret_cast<const ull*>(&Ws[wbase]);
#pragma unroll
                    for (int p = 0; p < NP; p++) w[p] = wp[p];
                } else {
                    if (NP > 0) w[0] = pack2(Ws[wbase], Ws[wbase + 1]);
                    wlast = Ws[wbase + O_PER - 1];
                }
#pragma unroll
                for (int rr = 0; rr < 4; rr++) {
                    float f = Fs[(ci * 128 + rr * 32 + lane) * 9 + g];
                    ull ff = pack2(f, f);
#pragma unroll
                    for (int p = 0; p < NP; p++) fma2(acc2[rr][p], w[p], ff);
                    if (ODD) accs[rr] = fmaf(wlast, f, accs[rr]);
                }
            }
        }
    }

    // epilogue
#pragma unroll
    for (int rr = 0; rr < 4; rr++) {
        int row = row0 + rr * 32 + lane;
#pragma unroll
        for (int p = 0; p < NP; p++) {
            float lo, hi;
            unpack2(acc2[rr][p], lo, hi);
            int o0 = og * O_PER + 2 * p;
            if (OUT_NCHW) {
                hout[(((row >> 12) * OUT + o0) << 12) + (row & 4095)] = lo;
                hout[(((row >> 12) * OUT + o0 + 1) << 12) + (row & 4095)] = hi;
            } else {
                hout[o0 * N + row] = lo;
                hout[(o0 + 1) * N + row] = hi;
            }
        }
        if (ODD) {
            int o = og * O_PER + O_PER - 1;
            if (OUT_NCHW)
                hout[(((row >> 12) * OUT + o) << 12) + (row & 4095)] = accs[rr];
            else
                hout[o * N + row] = accs[rr];
        }
    }
}

extern "C" void kernel_launch(void* const* d_in, const int* in_sizes, int n_in,
                              void* d_out, int out_size) {
    const float* x     = (const float*)d_in[0];
    const float* grid0 = (const float*)d_in[1];
    const float* coef0 = (const float*)d_in[2];
    const float* sb0   = (const float*)d_in[3];
    const float* ss0   = (const float*)d_in[4];
    const float* grid1 = (const float*)d_in[5];
    const float* coef1 = (const float*)d_in[6];
    const float* sb1   = (const float*)d_in[7];
    const float* ss1   = (const float*)d_in[8];
    const float* grid2 = (const float*)d_in[9];
    const float* coef2 = (const float*)d_in[10];
    const float* sb2   = (const float*)d_in[11];
    const float* ss2   = (const float*)d_in[12];

    float* out = (float*)d_out;

    int N = in_sizes[0] / 12;  // rows = B*H*W
    if (N > MAXN) N = MAXN;

    float *h1, *h2, *W0, *W1, *W2;
    cudaGetSymbolAddress((void**)&h1, g_h1);
    cudaGetSymbolAddress((void**)&h2, g_h2);
    cudaGetSymbolAddress((void**)&W0, g_W0);
    cudaGetSymbolAddress((void**)&W1, g_W1);
    cudaGetSymbolAddress((void**)&W2, g_W2);

    // fold weights
    fold_kernel<<<(12 * 9 * 64 + 255) / 256, 256>>>(coef0, sb0, ss0, W0, 12, 64);
    fold_kernel<<<(64 * 9 * 64 + 255) / 256, 256>>>(coef1, sb1, ss1, W1, 64, 64);
    fold_kernel<<<(64 * 9 * 24 + 255) / 256, 256>>>(coef2, sb2, ss2, W2, 64, 24);

    int blocks = N / 128;
    // layer 0: x is NCHW (per-batch planar), output planar [64][N]
    kan_layer<12, 64, 8, true, false><<<blocks, 256>>>(x, grid0, W0, h1, N);
    // layer 1: planar -> planar
    kan_layer<64, 64, 8, false, false><<<blocks, 256>>>(h1, grid1, W1, h2, N);
    // layer 2: planar -> NCHW output (32,24,64,64)
    kan_layer<64, 24, 3, false, true><<<blocks, 256>>>(h2, grid2, W2, out, N);
}

// round 3
// speedup vs baseline: 1.0063x; 1.0063x over previous
#include <cuda_runtime.h>
#include <cuda_bf16.h>
#include <cstdint>

// ---------------------------------------------------------------------------
// KAN 3-layer net (12->64->64->24) via warp-level split-bf16 mma.sync
// (m16n8k16, 3-pass hi/lo) on sm_103a. Features [silu, B0..B7] built
// in-kernel into swizzled SMEM; weights prefolded to bf16 hi/lo.
// ---------------------------------------------------------------------------

#define MAXN (32 * 64 * 64)

__device__ float g_h1[64 * MAXN];
__device__ float g_h2[64 * MAXN];
__device__ __align__(16) __nv_bfloat16 g_Whi0[64 * 128];
__device__ __align__(16) __nv_bfloat16 g_Wlo0[64 * 128];
__device__ __align__(16) __nv_bfloat16 g_Whi1[64 * 576];
__device__ __align__(16) __nv_bfloat16 g_Wlo1[64 * 576];
__device__ __align__(16) __nv_bfloat16 g_Whi2[24 * 576];
__device__ __align__(16) __nv_bfloat16 g_Wlo2[24 * 576];

// ------------------------------- helpers -----------------------------------

__device__ __forceinline__ uint32_t smem_u32(const void* p) {
    uint32_t a;
    asm("{ .reg .u64 t; cvta.to.shared.u64 t, %1; cvt.u32.u64 %0, t; }"
        : "=r"(a) : "l"(p));
    return a;
}

__device__ __forceinline__ uint32_t sw128(uint32_t off) {
    return off ^ ((off >> 3) & 0x70);
}

__device__ __forceinline__ void ldsm4(uint32_t addr, uint32_t r[4]) {
    asm volatile("ldmatrix.sync.aligned.m8n8.x4.shared.b16 {%0,%1,%2,%3}, [%4];"
                 : "=r"(r[0]), "=r"(r[1]), "=r"(r[2]), "=r"(r[3]) : "r"(addr));
}
__device__ __forceinline__ void ldsm2(uint32_t addr, uint32_t r[2]) {
    asm volatile("ldmatrix.sync.aligned.m8n8.x2.shared.b16 {%0,%1}, [%2];"
                 : "=r"(r[0]), "=r"(r[1]) : "r"(addr));
}

__device__ __forceinline__ void mma16816(float c[4], const uint32_t a[4],
                                         uint32_t b0, uint32_t b1) {
    asm volatile(
        "mma.sync.aligned.m16n8k16.row.col.f32.bf16.bf16.f32 "
        "{%0,%1,%2,%3},{%4,%5,%6,%7},{%8,%9},{%0,%1,%2,%3};"
        : "+f"(c[0]), "+f"(c[1]), "+f"(c[2]), "+f"(c[3])
        : "r"(a[0]), "r"(a[1]), "r"(a[2]), "r"(a[3]), "r"(b0), "r"(b1));
}

__device__ __forceinline__ void sts16(uint32_t addr, unsigned short v) {
    asm volatile("st.shared.b16 [%0], %1;" :: "r"(addr), "h"(v));
}
__device__ __forceinline__ void sts128(uint32_t addr, uint4 v) {
    asm volatile("st.shared.v4.b32 [%0], {%1,%2,%3,%4};"
                 :: "r"(addr), "r"(v.x), "r"(v.y), "r"(v.z), "r"(v.w));
}

// ------------------------------- fold kernel -------------------------------
// W[o][k]: k = i*9 + j; j==0 -> sb[i][o]; j==1+g -> coef[i][o][g]*ss[i][o].
__global__ void fold_hilo(const float* __restrict__ coef, const float* __restrict__ sbp,
                          const float* __restrict__ ss, __nv_bfloat16* __restrict__ Whi,
                          __nv_bfloat16* __restrict__ Wlo, int IN, int OUT, int KPAD) {
    int idx = blockIdx.x * blockDim.x + threadIdx.x;
    if (idx >= OUT * KPAD) return;
    int o = idx / KPAD, k = idx % KPAD;
    float w = 0.0f;
    if (k < IN * 9) {
        int i = k / 9, j = k % 9;
        w = (j == 0) ? sbp[i * OUT + o] : coef[(i * OUT + o) * 8 + (j - 1)] * ss[i * OUT + o];
    }
    __nv_bfloat16 hi = __float2bfloat16(w);
    __nv_bfloat16 lo = __float2bfloat16(w - __bfloat162float(hi));
    Whi[idx] = hi;
    Wlo[idx] = lo;
}

// ------------------------------- layer kernel ------------------------------
// Dynamic SMEM layout (1KB-aligned base):
//   [0,16K)     A_hi  128 rows x 64 bf16 (SW128)
//   [16K,32K)   A_lo
//   [32K,40K)   B_hi  OUT rows x 64 bf16 (SW128)
//   [40K,48K)   B_lo
static constexpr int SMEM_BYTES = 1024 + 2 * 16384 + 2 * 8192;  // 50176

template <int IN, int OUT, int K, int NCHUNK, bool IN_NCHW, bool OUT_NCHW>
__global__ void __launch_bounds__(256)
kan_mma(const float* __restrict__ hin, const float* __restrict__ grid,
        const __nv_bfloat16* __restrict__ Whi, const __nv_bfloat16* __restrict__ Wlo,
        float* __restrict__ hout, int N) {
    constexpr int KPAD = NCHUNK * 64;
    constexpr int NT = OUT / 8;    // n8 tiles
    constexpr int NT2 = NT / 2;

    extern __shared__ char dsm[];
    uint32_t sbase = (smem_u32(dsm) + 1023u) & ~1023u;
    const uint32_t Ahi = sbase, Alo = sbase + 16384;
    const uint32_t Bhi = sbase + 32768, Blo = sbase + 40960;

    const int tid = threadIdx.x;
    const int wid = tid >> 5;
    const int lane = tid & 31;
    const int row0 = blockIdx.x * 128;

    const float t0 = __ldg(grid + 0);
    const float invh = 1.0f / (__ldg(grid + 1) - t0);
    const float t11 = __ldg(grid + 11);

    // ldmatrix lane->address precompute
    const int gq = lane >> 3;
    const uint32_t a_base =
        (uint32_t)((wid * 16 + (lane & 7) + 8 * (gq & 1)) * 128 + (gq >> 1) * 16);
    const int brow = (lane & 7) + 8 * (gq >> 1);
    const int bseg = gq & 1;

    float acc[NT][4];
#pragma unroll
    for (int p = 0; p < NT; p++)
#pragma unroll
        for (int q = 0; q < 4; q++) acc[p][q] = 0.0f;

    for (int c = 0; c < NCHUNK; c++) {
        __syncthreads();  // previous chunk's MMA reads done; buffers free

        // ---- stage B chunk (hi & lo) as 16B vectors, swizzled ----
        {
            constexpr int UNITS = OUT * 8;  // 16B units per buffer
            for (int v = tid; v < 2 * UNITS; v += 256) {
                int h = v >= UNITS;
                int u = v - (h ? UNITS : 0);
                int o = u >> 3, seg = u & 7;
                const __nv_bfloat16* src = (h ? Wlo : Whi) + o * KPAD + c * 64 + seg * 8;
                uint4 val = *reinterpret_cast<const uint4*>(src);
                uint32_t off = sw128((uint32_t)(o * 128 + seg * 16));
                sts128((h ? Blo : Bhi) + off, val);
            }
        }

        // ---- feature generation into A chunk (hi & lo) ----
        {
            const int r = tid & 127;
            const int tq = tid >> 7;  // 0..1
            const int row = row0 + r;
            const int klo = c * 64;
            const int ilo = klo / 9;
            int ihi = (klo + 63) / 9;
            if (ihi > IN - 1) ihi = IN - 1;
            const uint32_t rbase = (uint32_t)(r * 128);

            for (int i = ilo + tq; i <= ihi; i += 2) {
                int idx;
                if (IN_NCHW) idx = ((row >> 12) * IN + i) * 4096 + (row & 4095);
                else idx = i * N + row;
                float x = __ldg(hin + idx);
                float f0 = __fdividef(x, 1.0f + __expf(-x));  // silu

                float v0 = 0.f, v1 = 0.f, v2 = 0.f, v3 = 0.f;
                int m = -100;
                if (x >= t0 && x < t11) {
                    float s = (x - t0) * invh;
                    m = (int)s;
                    if (m > 10) m = 10;
                    float u1 = s - (float)m;
                    float um = 1.0f - u1;
                    float u2 = u1 * u1, u3 = u2 * u1;
                    v0 = um * um * um * (1.0f / 6.0f);
                    v1 = (3.0f * u3 - 6.0f * u2 + 4.0f) * (1.0f / 6.0f);
                    v2 = (-3.0f * u3 + 3.0f * u2 + 3.0f * u1 + 1.0f) * (1.0f / 6.0f);
                    v3 = u3 * (1.0f / 6.0f);
                }
                const int kb = i * 9 - klo;
#pragma unroll
                for (int j = 0; j < 9; j++) {
                    int kk = kb + j;
                    if (kk < 0 || kk >= 64) continue;
                    float v;
                    if (j == 0) v = f0;
                    else {
                        int gg = (j - 1) - m + 3;  // 0..3 inside window
                        v = (gg == 0) ? v0 : (gg == 1) ? v1 : (gg == 2) ? v2
                            : (gg == 3) ? v3 : 0.0f;
                    }
                    __nv_bfloat16 h16 = __float2bfloat16(v);
                    __nv_bfloat16 l16 = __float2bfloat16(v - __bfloat162float(h16));
                    uint32_t off = sw128(rbase + (uint32_t)(kk * 2));
                    sts16(Ahi + off, __bfloat16_as_ushort(h16));
                    sts16(Alo + off, __bfloat16_as_ushort(l16));
                }
            }

            if constexpr (K < KPAD) {  // zero pad cols in last chunk (layer 0)
                constexpr int PADC = KPAD - K;
                if (c == NCHUNK - 1) {
                    for (int z = tid; z < PADC * 128; z += 256) {
                        int rr = z & 127;
                        int kk = 64 - PADC + (z >> 7);
                        uint32_t off = sw128((uint32_t)(rr * 128 + kk * 2));
                        sts16(Ahi + off, 0);
                        sts16(Alo + off, 0);
                    }
                }
            }
        }

        __syncthreads();

        // ---- MMA phase: 4 k-steps of 16, 3 passes (hh, hl, lh) ----
#pragma unroll
        for (int ks = 0; ks < 4; ks++) {
            uint32_t asw = sw128(a_base + (uint32_t)(ks * 32));
            uint32_t ah[4], al[4];
            ldsm4(Ahi + asw, ah);
            ldsm4(Alo + asw, al);
#pragma unroll
            for (int q = 0; q < NT2; q++) {
                uint32_t bo = sw128((uint32_t)((16 * q + brow) * 128 + bseg * 16 + ks * 32));
                uint32_t bh[4], bl[4];
                ldsm4(Bhi + bo, bh);
                ldsm4(Blo + bo, bl);
                mma16816(acc[2 * q], ah, bh[0], bh[1]);
                mma16816(acc[2 * q + 1], ah, bh[2], bh[3]);
                mma16816(acc[2 * q], ah, bl[0], bl[1]);
                mma16816(acc[2 * q + 1], ah, bl[2], bl[3]);
                mma16816(acc[2 * q], al, bh[0], bh[1]);
                mma16816(acc[2 * q + 1], al, bh[2], bh[3]);
            }
            if constexpr (NT & 1) {
                uint32_t bo = sw128((uint32_t)((8 * (NT - 1) + (lane & 7)) * 128 +
                                               ((lane >> 3) & 1) * 16 + ks * 32));
                uint32_t bh2[2], bl2[2];
                ldsm2(Bhi + bo, bh2);
                ldsm2(Blo + bo, bl2);
                mma16816(acc[NT - 1], ah, bh2[0], bh2[1]);
                mma16816(acc[NT - 1], ah, bl2[0], bl2[1]);
                mma16816(acc[NT - 1], al, bh2[0], bh2[1]);
            }
        }
    }

    // ---- epilogue: write accumulators ----
    const int r0 = row0 + wid * 16 + (lane >> 2);
    const int r1 = r0 + 8;
#pragma unroll
    for (int p = 0; p < NT; p++) {
        int o = p * 8 + (lane & 3) * 2;
        if (OUT_NCHW) {
            int b0 = r0 >> 12, p0 = r0 & 4095;
            int b1 = r1 >> 12, p1 = r1 & 4095;
            hout[(b0 * OUT + o) * 4096 + p0] = acc[p][0];
            hout[(b0 * OUT + o + 1) * 4096 + p0] = acc[p][1];
            hout[(b1 * OUT + o) * 4096 + p1] = acc[p][2];
            hout[(b1 * OUT + o + 1) * 4096 + p1] = acc[p][3];
        } else {
            hout[o * N + r0] = acc[p][0];
            hout[(o + 1) * N + r0] = acc[p][1];
            hout[o * N + r1] = acc[p][2];
            hout[(o + 1) * N + r1] = acc[p][3];
        }
    }
}

// ------------------------------- launch ------------------------------------

extern "C" void kernel_launch(void* const* d_in, const int* in_sizes, int n_in,
                              void* d_out, int out_size) {
    const float* x     = (const float*)d_in[0];
    const float* grid0 = (const float*)d_in[1];
    const float* coef0 = (const float*)d_in[2];
    const float* sb0   = (const float*)d_in[3];
    const float* ss0   = (const float*)d_in[4];
    const float* grid1 = (const float*)d_in[5];
    const float* coef1 = (const float*)d_in[6];
    const float* sb1   = (const float*)d_in[7];
    const float* ss1   = (const float*)d_in[8];
    const float* grid2 = (const float*)d_in[9];
    const float* coef2 = (const float*)d_in[10];
    const float* sb2   = (const float*)d_in[11];
    const float* ss2   = (const float*)d_in[12];
    float* out = (float*)d_out;

    int N = in_sizes[0] / 12;
    if (N > MAXN) N = MAXN;

    float *h1, *h2;
    __nv_bfloat16 *Whi0, *Wlo0, *Whi1, *Wlo1, *Whi2, *Wlo2;
    cudaGetSymbolAddress((void**)&h1, g_h1);
    cudaGetSymbolAddress((void**)&h2, g_h2);
    cudaGetSymbolAddress((void**)&Whi0, g_Whi0);
    cudaGetSymbolAddress((void**)&Wlo0, g_Wlo0);
    cudaGetSymbolAddress((void**)&Whi1, g_Whi1);
    cudaGetSymbolAddress((void**)&Wlo1, g_Wlo1);
    cudaGetSymbolAddress((void**)&Whi2, g_Whi2);
    cudaGetSymbolAddress((void**)&Wlo2, g_Wlo2);

    fold_hilo<<<(64 * 128 + 255) / 256, 256>>>(coef0, sb0, ss0, Whi0, Wlo0, 12, 64, 128);
    fold_hilo<<<(64 * 576 + 255) / 256, 256>>>(coef1, sb1, ss1, Whi1, Wlo1, 64, 64, 576);
    fold_hilo<<<(24 * 576 + 255) / 256, 256>>>(coef2, sb2, ss2, Whi2, Wlo2, 64, 24, 576);

    auto k0 = kan_mma<12, 64, 108, 2, true, false>;
    auto k1 = kan_mma<64, 64, 576, 9, false, false>;
    auto k2 = kan_mma<64, 24, 576, 9, false, true>;
    cudaFuncSetAttribute(k0, cudaFuncAttributeMaxDynamicSharedMemorySize, SMEM_BYTES);
    cudaFuncSetAttribute(k1, cudaFuncAttributeMaxDynamicSharedMemorySize, SMEM_BYTES);
    cudaFuncSetAttribute(k2, cudaFuncAttributeMaxDynamicSharedMemorySize, SMEM_BYTES);

    int blocks = N / 128;
    k0<<<blocks, 256, SMEM_BYTES>>>(x, grid0, Whi0, Wlo0, h1, N);
    k1<<<blocks, 256, SMEM_BYTES>>>(h1, grid1, Whi1, Wlo1, h2, N);
    k2<<<blocks, 256, SMEM_BYTES>>>(h2, grid2, Whi2, Wlo2, out, N);
}

// round 4
// speedup vs baseline: 1.2200x; 1.2123x over previous
#include <cuda_runtime.h>
#include <cuda_bf16.h>
#include <cstdint>

// ---------------------------------------------------------------------------
// KAN 3-layer (12->64->64->24) via warp mma.sync bf16 3-pass (hi/lo split).
// Per CTA: 64 rows. Features scattered (5 nonzero of 9) into zeroed, swizzled
// SMEM chunks of 64 K-cols; ping-pong buffers overlap feature-gen with MMA.
// ---------------------------------------------------------------------------

#define MAXN (32 * 64 * 64)

__device__ float g_h1[64 * MAXN];
__device__ float g_h2[64 * MAXN];
__device__ __align__(16) __nv_bfloat16 g_Whi0[64 * 128];
__device__ __align__(16) __nv_bfloat16 g_Wlo0[64 * 128];
__device__ __align__(16) __nv_bfloat16 g_Whi1[64 * 576];
__device__ __align__(16) __nv_bfloat16 g_Wlo1[64 * 576];
__device__ __align__(16) __nv_bfloat16 g_Whi2[24 * 576];
__device__ __align__(16) __nv_bfloat16 g_Wlo2[24 * 576];

// ------------------------------- helpers -----------------------------------

__device__ __forceinline__ uint32_t smem_u32(const void* p) {
    uint32_t a;
    asm("{ .reg .u64 t; cvta.to.shared.u64 t, %1; cvt.u32.u64 %0, t; }"
        : "=r"(a) : "l"(p));
    return a;
}
__device__ __forceinline__ uint32_t sw128(uint32_t off) {
    return off ^ ((off >> 3) & 0x70);
}
__device__ __forceinline__ void ldsm4(uint32_t addr, uint32_t r[4]) {
    asm volatile("ldmatrix.sync.aligned.m8n8.x4.shared.b16 {%0,%1,%2,%3}, [%4];"
                 : "=r"(r[0]), "=r"(r[1]), "=r"(r[2]), "=r"(r[3]) : "r"(addr));
}
__device__ __forceinline__ void ldsm2(uint32_t addr, uint32_t r[2]) {
    asm volatile("ldmatrix.sync.aligned.m8n8.x2.shared.b16 {%0,%1}, [%2];"
                 : "=r"(r[0]), "=r"(r[1]) : "r"(addr));
}
__device__ __forceinline__ void mma16816(float c[4], const uint32_t a[4],
                                         uint32_t b0, uint32_t b1) {
    asm volatile(
        "mma.sync.aligned.m16n8k16.row.col.f32.bf16.bf16.f32 "
        "{%0,%1,%2,%3},{%4,%5,%6,%7},{%8,%9},{%0,%1,%2,%3};"
        : "+f"(c[0]), "+f"(c[1]), "+f"(c[2]), "+f"(c[3])
        : "r"(a[0]), "r"(a[1]), "r"(a[2]), "r"(a[3]), "r"(b0), "r"(b1));
}
__device__ __forceinline__ void sts16(uint32_t addr, unsigned short v) {
    asm volatile("st.shared.b16 [%0], %1;" :: "r"(addr), "h"(v));
}
__device__ __forceinline__ void sts128(uint32_t addr, uint4 v) {
    asm volatile("st.shared.v4.b32 [%0], {%1,%2,%3,%4};"
                 :: "r"(addr), "r"(v.x), "r"(v.y), "r"(v.z), "r"(v.w));
}

// hi/lo bf16 split of fp32 value
__device__ __forceinline__ void split_hl(float v, unsigned short& h, unsigned short& l) {
    __nv_bfloat16 hb = __float2bfloat16(v);
    float hf = __bfloat162float(hb);
    __nv_bfloat16 lb = __float2bfloat16(v - hf);
    h = __bfloat16_as_ushort(hb);
    l = __bfloat16_as_ushort(lb);
}

// ------------------------------- fold kernel -------------------------------
__global__ void fold_hilo(const float* __restrict__ coef, const float* __restrict__ sbp,
                          const float* __restrict__ ss, __nv_bfloat16* __restrict__ Whi,
                          __nv_bfloat16* __restrict__ Wlo, int IN, int OUT, int KPAD) {
    int idx = blockIdx.x * blockDim.x + threadIdx.x;
    if (idx >= OUT * KPAD) return;
    int o = idx / KPAD, k = idx % KPAD;
    float w = 0.0f;
    if (k < IN * 9) {
        int i = k / 9, j = k % 9;
        w = (j == 0) ? sbp[i * OUT + o] : coef[(i * OUT + o) * 8 + (j - 1)] * ss[i * OUT + o];
    }
    __nv_bfloat16 hi = __float2bfloat16(w);
    __nv_bfloat16 lo = __float2bfloat16(w - __bfloat162float(hi));
    Whi[idx] = hi;
    Wlo[idx] = lo;
}

// ------------------------------- layer kernel ------------------------------
// SMEM: A[stage][hi/lo] 8KB each (64 rows x 64 bf16, SW128) = 32KB
//       B[stage][hi/lo] OUT*128B each
template <int IN, int OUT, int KPAD, int NCHUNK, bool IN_NCHW, bool OUT_NCHW>
__global__ void __launch_bounds__(128)
kan_mma(const float* __restrict__ hin, const float* __restrict__ grid,
        const __nv_bfloat16* __restrict__ Whi, const __nv_bfloat16* __restrict__ Wlo,
        float* __restrict__ hout, int N) {
    constexpr int NT = OUT / 8;
    constexpr int NT2 = NT / 2;
    constexpr int ABUF = 64 * 128;   // 8KB per A buffer
    constexpr int BBUF = OUT * 128;

    extern __shared__ char dsm[];
    const uint32_t sb = smem_u32(dsm);
    const uint32_t BBASE = sb + 4 * ABUF;

    const int tid = threadIdx.x;
    const int wid = tid >> 5;
    const int lane = tid & 31;
    const int row0 = blockIdx.x * 64;

    const float t0 = __ldg(grid + 0);
    const float invh = 1.0f / (__ldg(grid + 1) - t0);
    const float t11 = __ldg(grid + 11);

    // precomputed per-thread constants for scatter
    const int r = tid & 63;
    const int half = tid >> 6;
    const int rowg = row0 + r;
    const int img = rowg >> 12;
    const int pix = rowg & 4095;
    const uint32_t rbase = (uint32_t)(r * 128);

    // ldmatrix fragment addressing (warp covers rows wid*16..+15)
    const int gq = lane >> 3;
    const uint32_t a_base =
        (uint32_t)((wid * 16 + (lane & 7) + 8 * (gq & 1)) * 128 + (gq >> 1) * 16);
    const int brow = (lane & 7) + 8 * (gq >> 1);
    const int bseg = gq & 1;

    float acc[NT][4];
#pragma unroll
    for (int p = 0; p < NT; p++)
#pragma unroll
        for (int q = 0; q < 4; q++) acc[p][q] = 0.0f;

    // ---------------- staging helpers (inlined lambdas) ----------------
    auto zeroA = [&](int st) {
        uint4 z = make_uint4(0, 0, 0, 0);
        uint32_t a0 = sb + (uint32_t)(st * 2) * ABUF + (uint32_t)tid * 64;
#pragma unroll
        for (int j = 0; j < 4; j++) {
            sts128(a0 + j * 16, z);
            sts128(a0 + ABUF + j * 16, z);
        }
    };

    auto stageB = [&](int c, int st) {
        uint32_t bb = BBASE + (uint32_t)(st * 2) * BBUF;
        for (int v = tid; v < OUT * 16; v += 128) {
            int h = v >= OUT * 8;
            int u = v - (h ? OUT * 8 : 0);
            int o = u >> 3, seg = u & 7;
            const __nv_bfloat16* src = (h ? Wlo : Whi) + o * KPAD + c * 64 + seg * 8;
            uint4 val = *reinterpret_cast<const uint4*>(src);
            sts128(bb + (uint32_t)h * BBUF + sw128((uint32_t)(o * 128 + seg * 16)), val);
        }
    };

    auto scatter = [&](int c, int st) {
        const uint32_t ah = sb + (uint32_t)(st * 2) * ABUF;
        const int klo = c * 64;
        const int ilo = klo / 9;
        int ihi = (klo + 63) / 9;
        if (ihi > IN - 1) ihi = IN - 1;
        for (int i = ilo + half; i <= ihi; i += 2) {
            int idx;
            if (IN_NCHW) idx = (img * IN + i) * 4096 + pix;
            else idx = i * N + rowg;
            float x = __ldg(hin + idx);
            float e = __expf(-x);
            float f0 = __fdividef(x, 1.0f + e);  // silu

            bool inr = (x >= t0) && (x < t11);
            float s = (x - t0) * invh;
            s = fminf(fmaxf(s, 0.0f), 10.999f);
            int m = (int)s;
            float u1 = s - (float)m;
            float um = 1.0f - u1;
            float u2 = u1 * u1, u3 = u2 * u1;
            float fl = inr ? (1.0f / 6.0f) : 0.0f;
            float v0 = um * um * um * fl;
            float v1 = (3.0f * u3 - 6.0f * u2 + 4.0f) * fl;
            float v2 = (-3.0f * u3 + 3.0f * u2 + 3.0f * u1 + 1.0f) * fl;
            float v3 = u3 * fl;

            const int kb = i * 9 - klo;
            unsigned short hh, ll;
            // silu at slot j=0 (k = kb)
            if ((unsigned)kb < 64u) {
                split_hl(f0, hh, ll);
                uint32_t off = sw128(rbase + (uint32_t)(kb * 2));
                sts16(ah + off, hh);
                sts16(ah + ABUF + off, ll);
            }
            // window values at basis index bi = m-3+g, slot j = 1+bi
            const int kw = kb + m - 2;  // k for g=0
#pragma unroll
            for (int g = 0; g < 4; g++) {
                int bi = m - 3 + g;
                int k = kw + g;
                float v = (g == 0) ? v0 : (g == 1) ? v1 : (g == 2) ? v2 : v3;
                if ((unsigned)bi <= 7u && (unsigned)k < 64u) {
                    split_hl(v, hh, ll);
                    uint32_t off = sw128(rbase + (uint32_t)(k * 2));
                    sts16(ah + off, hh);
                    sts16(ah + ABUF + off, ll);
                }
            }
        }
    };

    // ---------------- main pipeline ----------------
    zeroA(0);
    __syncthreads();
    scatter(0, 0);
    stageB(0, 0);

    for (int c = 0; c < NCHUNK; c++) {
        const int st = c & 1;
        __syncthreads();  // staging(c) complete; mma(c-1) complete
        if (c + 1 < NCHUNK) zeroA(st ^ 1);
        __syncthreads();  // zero complete before scatter into same buffer
        if (c + 1 < NCHUNK) {
            scatter(c + 1, st ^ 1);
            stageB(c + 1, st ^ 1);
        }

        // ---- MMA on chunk c (buffers st): 4 ksteps, 3 passes ----
        const uint32_t Ah = sb + (uint32_t)(st * 2) * ABUF;
        const uint32_t Al = Ah + ABUF;
        const uint32_t Bh = BBASE + (uint32_t)(st * 2) * BBUF;
        const uint32_t Bl = Bh + BBUF;
#pragma unroll
        for (int ks = 0; ks < 4; ks++) {
            uint32_t asw = sw128(a_base + (uint32_t)(ks * 32));
            uint32_t ah[4], al[4];
            ldsm4(Ah + asw, ah);
            ldsm4(Al + asw, al);
#pragma unroll
            for (int q = 0; q < NT2; q++) {
                uint32_t bo = sw128((uint32_t)((16 * q + brow) * 128 + bseg * 16 + ks * 32));
                uint32_t bh[4], bl[4];
                ldsm4(Bh + bo, bh);
                ldsm4(Bl + bo, bl);
                mma16816(acc[2 * q], ah, bh[0], bh[1]);
                mma16816(acc[2 * q + 1], ah, bh[2], bh[3]);
                mma16816(acc[2 * q], ah, bl[0], bl[1]);
                mma16816(acc[2 * q + 1], ah, bl[2], bl[3]);
                mma16816(acc[2 * q], al, bh[0], bh[1]);
                mma16816(acc[2 * q + 1], al, bh[2], bh[3]);
            }
            if constexpr (NT & 1) {
                uint32_t bo = sw128((uint32_t)((8 * (NT - 1) + (lane & 7)) * 128 +
                                               ((lane >> 3) & 1) * 16 + ks * 32));
                uint32_t bh2[2], bl2[2];
                ldsm2(Bh + bo, bh2);
                ldsm2(Bl + bo, bl2);
                mma16816(acc[NT - 1], ah, bh2[0], bh2[1]);
                mma16816(acc[NT - 1], ah, bl2[0], bl2[1]);
                mma16816(acc[NT - 1], al, bh2[0], bh2[1]);
            }
        }
    }

    // ---------------- epilogue: smem transpose -> coalesced STG ----------------
    __syncthreads();
    float* S = reinterpret_cast<float*>(dsm);  // reuse A region: OUT*65*4 bytes
    {
        const int er0 = wid * 16 + (lane >> 2);
        const int er1 = er0 + 8;
#pragma unroll
        for (int p = 0; p < NT; p++) {
            int o = p * 8 + (lane & 3) * 2;
            S[o * 65 + er0] = acc[p][0];
            S[(o + 1) * 65 + er0] = acc[p][1];
            S[o * 65 + er1] = acc[p][2];
            S[(o + 1) * 65 + er1] = acc[p][3];
        }
    }
    __syncthreads();
    for (int idx = tid; idx < OUT * 64; idx += 128) {
        int o = idx >> 6;
        int rr = idx & 63;
        float val = S[o * 65 + rr];
        if (OUT_NCHW) hout[((row0 >> 12) * OUT + o) * 4096 + (row0 & 4095) + rr] = val;
        else hout[o * N + row0 + rr] = val;
    }
}

// ------------------------------- launch ------------------------------------

extern "C" void kernel_launch(void* const* d_in, const int* in_sizes, int n_in,
                              void* d_out, int out_size) {
    const float* x     = (const float*)d_in[0];
    const float* grid0 = (const float*)d_in[1];
    const float* coef0 = (const float*)d_in[2];
    const float* sb0   = (const float*)d_in[3];
    const float* ss0   = (const float*)d_in[4];
    const float* grid1 = (const float*)d_in[5];
    const float* coef1 = (const float*)d_in[6];
    const float* sb1   = (const float*)d_in[7];
    const float* ss1   = (const float*)d_in[8];
    const float* grid2 = (const float*)d_in[9];
    const float* coef2 = (const float*)d_in[10];
    const float* sb2   = (const float*)d_in[11];
    const float* ss2   = (const float*)d_in[12];
    float* out = (float*)d_out;

    int N = in_sizes[0] / 12;
    if (N > MAXN) N = MAXN;

    float *h1, *h2;
    __nv_bfloat16 *Whi0, *Wlo0, *Whi1, *Wlo1, *Whi2, *Wlo2;
    cudaGetSymbolAddress((void**)&h1, g_h1);
    cudaGetSymbolAddress((void**)&h2, g_h2);
    cudaGetSymbolAddress((void**)&Whi0, g_Whi0);
    cudaGetSymbolAddress((void**)&Wlo0, g_Wlo0);
    cudaGetSymbolAddress((void**)&Whi1, g_Whi1);
    cudaGetSymbolAddress((void**)&Wlo1, g_Wlo1);
    cudaGetSymbolAddress((void**)&Whi2, g_Whi2);
    cudaGetSymbolAddress((void**)&Wlo2, g_Wlo2);

    fold_hilo<<<(64 * 128 + 255) / 256, 256>>>(coef0, sb0, ss0, Whi0, Wlo0, 12, 64, 128);
    fold_hilo<<<(64 * 576 + 255) / 256, 256>>>(coef1, sb1, ss1, Whi1, Wlo1, 64, 64, 576);
    fold_hilo<<<(24 * 576 + 255) / 256, 256>>>(coef2, sb2, ss2, Whi2, Wlo2, 64, 24, 576);

    auto k0 = kan_mma<12, 64, 128, 2, true, false>;
    auto k1 = kan_mma<64, 64, 576, 9, false, false>;
    auto k2 = kan_mma<64, 24, 576, 9, false, true>;

    constexpr int SM01 = 4 * 64 * 128 + 4 * 64 * 128;  // 65536
    constexpr int SM2  = 4 * 64 * 128 + 4 * 24 * 128;  // 45056
    cudaFuncSetAttribute(k0, cudaFuncAttributeMaxDynamicSharedMemorySize, SM01);
    cudaFuncSetAttribute(k1, cudaFuncAttributeMaxDynamicSharedMemorySize, SM01);
    cudaFuncSetAttribute(k2, cudaFuncAttributeMaxDynamicSharedMemorySize, SM2);

    int blocks = N / 64;
    k0<<<blocks, 128, SM01>>>(x, grid0, Whi0, Wlo0, h1, N);
    k1<<<blocks, 128, SM01>>>(h1, grid1, Whi1, Wlo1, h2, N);
    k2<<<blocks, 128, SM2>>>(h2, grid2, Whi2, Wlo2, out, N);
}

// round 5
// speedup vs baseline: 1.4515x; 1.1898x over previous
#include <cuda_runtime.h>
#include <cuda_bf16.h>
#include <cstdint>

// ---------------------------------------------------------------------------
// KAN 3-layer (12->64->64->24) via warp mma.sync bf16 3-pass (hi/lo split).
// 256 threads / 128 rows per CTA. Pipelined: x prefetched to regs one chunk
// ahead, B staged via cp.async one chunk ahead, one barrier per chunk,
// same-thread window zeroing (no zero pass).
// ---------------------------------------------------------------------------

#define MAXN (32 * 64 * 64)

__device__ float g_h1[64 * MAXN];
__device__ float g_h2[64 * MAXN];
__device__ __align__(16) __nv_bfloat16 g_Whi0[64 * 128];
__device__ __align__(16) __nv_bfloat16 g_Wlo0[64 * 128];
__device__ __align__(16) __nv_bfloat16 g_Whi1[64 * 576];
__device__ __align__(16) __nv_bfloat16 g_Wlo1[64 * 576];
__device__ __align__(16) __nv_bfloat16 g_Whi2[24 * 576];
__device__ __align__(16) __nv_bfloat16 g_Wlo2[24 * 576];

// ------------------------------- helpers -----------------------------------

__device__ __forceinline__ uint32_t smem_u32(const void* p) {
    uint32_t a;
    asm("{ .reg .u64 t; cvta.to.shared.u64 t, %1; cvt.u32.u64 %0, t; }"
        : "=r"(a) : "l"(p));
    return a;
}
__device__ __forceinline__ uint32_t sw128(uint32_t off) {
    return off ^ ((off >> 3) & 0x70);
}
__device__ __forceinline__ void ldsm4(uint32_t addr, uint32_t r[4]) {
    asm volatile("ldmatrix.sync.aligned.m8n8.x4.shared.b16 {%0,%1,%2,%3}, [%4];"
                 : "=r"(r[0]), "=r"(r[1]), "=r"(r[2]), "=r"(r[3]) : "r"(addr));
}
__device__ __forceinline__ void ldsm2(uint32_t addr, uint32_t r[2]) {
    asm volatile("ldmatrix.sync.aligned.m8n8.x2.shared.b16 {%0,%1}, [%2];"
                 : "=r"(r[0]), "=r"(r[1]) : "r"(addr));
}
__device__ __forceinline__ void mma16816(float c[4], const uint32_t a[4],
                                         uint32_t b0, uint32_t b1) {
    asm volatile(
        "mma.sync.aligned.m16n8k16.row.col.f32.bf16.bf16.f32 "
        "{%0,%1,%2,%3},{%4,%5,%6,%7},{%8,%9},{%0,%1,%2,%3};"
        : "+f"(c[0]), "+f"(c[1]), "+f"(c[2]), "+f"(c[3])
        : "r"(a[0]), "r"(a[1]), "r"(a[2]), "r"(a[3]), "r"(b0), "r"(b1));
}
__device__ __forceinline__ void sts16(uint32_t addr, unsigned short v) {
    asm volatile("st.shared.b16 [%0], %1;" :: "r"(addr), "h"(v));
}
__device__ __forceinline__ void cp16(uint32_t dst, const void* src) {
    asm volatile("cp.async.ca.shared.global [%0], [%1], 16;"
                 :: "r"(dst), "l"(src) : "memory");
}
__device__ __forceinline__ void cp_commit() {
    asm volatile("cp.async.commit_group;" ::: "memory");
}
__device__ __forceinline__ void cp_wait0() {
    asm volatile("cp.async.wait_group 0;" ::: "memory");
}
__device__ __forceinline__ void split_hl(float v, unsigned short& h, unsigned short& l) {
    __nv_bfloat16 hb = __float2bfloat16(v);
    float hf = __bfloat162float(hb);
    __nv_bfloat16 lb = __float2bfloat16(v - hf);
    h = __bfloat16_as_ushort(hb);
    l = __bfloat16_as_ushort(lb);
}

// ------------------------------- fold kernel -------------------------------
__global__ void fold_hilo(const float* __restrict__ coef, const float* __restrict__ sbp,
                          const float* __restrict__ ss, __nv_bfloat16* __restrict__ Whi,
                          __nv_bfloat16* __restrict__ Wlo, int IN, int OUT, int KPAD) {
    int idx = blockIdx.x * blockDim.x + threadIdx.x;
    if (idx >= OUT * KPAD) return;
    int o = idx / KPAD, k = idx % KPAD;
    float w = 0.0f;
    if (k < IN * 9) {
        int i = k / 9, j = k % 9;
        w = (j == 0) ? sbp[i * OUT + o] : coef[(i * OUT + o) * 8 + (j - 1)] * ss[i * OUT + o];
    }
    __nv_bfloat16 hi = __float2bfloat16(w);
    __nv_bfloat16 lo = __float2bfloat16(w - __bfloat162float(hi));
    Whi[idx] = hi;
    Wlo[idx] = lo;
}

// ------------------------------- layer kernel ------------------------------
// SMEM: A[stage][hi/lo] 16KB each (128 rows x 64 bf16, SW128) = 64KB
//       B[stage][hi/lo] OUT*128B each
template <int IN, int OUT, int K, int KPAD, int NCHUNK, bool IN_NCHW, bool OUT_NCHW>
__global__ void __launch_bounds__(256, 2)
kan_mma(const float* __restrict__ hin, const float* __restrict__ grid,
        const __nv_bfloat16* __restrict__ Whi, const __nv_bfloat16* __restrict__ Wlo,
        float* __restrict__ hout, int N) {
    constexpr int NT = OUT / 8;
    constexpr int NT2 = NT / 2;
    constexpr int ABUF = 128 * 128;  // 16KB per A buffer
    constexpr int BBUF = OUT * 128;

    extern __shared__ char dsm[];
    const uint32_t sb = smem_u32(dsm);
    const uint32_t BBASE = sb + 4 * ABUF;

    const int tid = threadIdx.x;
    const int wid = tid >> 5;
    const int lane = tid & 31;
    const int row0 = blockIdx.x * 128;

    const float t0 = __ldg(grid + 0);
    const float invh = 1.0f / (__ldg(grid + 1) - t0);
    const float t11 = __ldg(grid + 11);

    const int r = tid & 127;
    const int half = tid >> 7;
    const int rowg = row0 + r;
    const int img = rowg >> 12;
    const int pix = rowg & 4095;
    const uint32_t rbase = (uint32_t)(r * 128);

    // ldmatrix fragment addressing
    const int gq = lane >> 3;
    const uint32_t a_base =
        (uint32_t)((wid * 16 + (lane & 7) + 8 * (gq & 1)) * 128 + (gq >> 1) * 16);
    const int brow = (lane & 7) + 8 * (gq >> 1);
    const int bseg = gq & 1;

    float acc[NT][4];
#pragma unroll
    for (int p = 0; p < NT; p++)
#pragma unroll
        for (int q = 0; q < 4; q++) acc[p][q] = 0.0f;

    // ---------------- pipeline helpers ----------------
    auto prefetch = [&](int c, float* xr) {
        const int klo = c * 64;
        const int ilo = klo / 9;
        int ihi = (klo + 63) / 9;
        if (ihi > IN - 1) ihi = IN - 1;
#pragma unroll
        for (int q = 0; q < 5; q++) {
            int i = ilo + half + 2 * q;
            int idx;
            if (IN_NCHW) idx = (img * IN + i) * 4096 + pix;
            else idx = i * N + rowg;
            xr[q] = (i <= ihi) ? __ldg(hin + idx) : 0.0f;
        }
    };

    auto stageB = [&](int c, int st) {
        uint32_t bb = BBASE + (uint32_t)(st * 2) * BBUF;
        for (int v = tid; v < OUT * 16; v += 256) {
            int h = v >= OUT * 8;
            int u = v - (h ? OUT * 8 : 0);
            int o = u >> 3, seg = u & 7;
            const __nv_bfloat16* src = (h ? Wlo : Whi) + o * KPAD + c * 64 + seg * 8;
            cp16(bb + (uint32_t)h * BBUF + sw128((uint32_t)(o * 128 + seg * 16)), src);
        }
        cp_commit();
    };

    auto scatter = [&](int c, int st, const float* xr) {
        const uint32_t ah = sb + (uint32_t)(st * 2) * ABUF;
        const int klo = c * 64;
        const int ilo = klo / 9;
        int ihi = (klo + 63) / 9;
        if (ihi > IN - 1) ihi = IN - 1;
#pragma unroll
        for (int q = 0; q < 5; q++) {
            int i = ilo + half + 2 * q;
            if (i > ihi) break;
            float x = xr[q];
            float f0 = __fdividef(x, 1.0f + __expf(-x));  // silu

            bool inr = (x >= t0) && (x < t11);
            float s = (x - t0) * invh;
            s = fminf(fmaxf(s, 0.0f), 10.999f);
            int m = (int)s;
            float u1 = s - (float)m;
            float um = 1.0f - u1;
            float u2 = u1 * u1, u3 = u2 * u1;
            float fl = inr ? (1.0f / 6.0f) : 0.0f;
            float v0 = um * um * um * fl;
            float v1 = (3.0f * u3 - 6.0f * u2 + 4.0f) * fl;
            float v2 = (-3.0f * u3 + 3.0f * u2 + 3.0f * u1 + 1.0f) * fl;
            float v3 = u3 * fl;

            const int kb = i * 9 - klo;
            // zero this input's basis slots (j=1..8); silu slot always written
#pragma unroll
            for (int j = 1; j < 9; j++) {
                int k = kb + j;
                if ((unsigned)k < 64u) {
                    uint32_t off = sw128(rbase + (uint32_t)(k * 2));
                    sts16(ah + off, 0);
                    sts16(ah + ABUF + off, 0);
                }
            }
            unsigned short hh, ll;
            if ((unsigned)kb < 64u) {  // silu slot
                split_hl(f0, hh, ll);
                uint32_t off = sw128(rbase + (uint32_t)(kb * 2));
                sts16(ah + off, hh);
                sts16(ah + ABUF + off, ll);
            }
            const int kw = kb + m - 2;  // k for g=0
#pragma unroll
            for (int g = 0; g < 4; g++) {
                int bi = m - 3 + g;
                int k = kw + g;
                float v = (g == 0) ? v0 : (g == 1) ? v1 : (g == 2) ? v2 : v3;
                if ((unsigned)bi <= 7u && (unsigned)k < 64u) {
                    split_hl(v, hh, ll);
                    uint32_t off = sw128(rbase + (uint32_t)(k * 2));
                    sts16(ah + off, hh);
                    sts16(ah + ABUF + off, ll);
                }
            }
        }
        // tail zero for layer0 last chunk (cols K-klo .. 63 never covered)
        if (K < KPAD && c == NCHUNK - 1) {
            constexpr int PADC = 64 - (K & 63);  // 20 for K=108
            int base = 64 - PADC + (PADC / 2) * half;
#pragma unroll
            for (int j = 0; j < PADC / 2; j++) {
                uint32_t off = sw128(rbase + (uint32_t)((base + j) * 2));
                sts16(ah + off, 0);
                sts16(ah + ABUF + off, 0);
            }
        }
    };

    auto mma_chunk = [&](int st) {
        const uint32_t Ah = sb + (uint32_t)(st * 2) * ABUF;
        const uint32_t Al = Ah + ABUF;
        const uint32_t Bh = BBASE + (uint32_t)(st * 2) * BBUF;
        const uint32_t Bl = Bh + BBUF;
#pragma unroll
        for (int ks = 0; ks < 4; ks++) {
            uint32_t asw = sw128(a_base + (uint32_t)(ks * 32));
            uint32_t ah[4], al[4];
            ldsm4(Ah + asw, ah);
            ldsm4(Al + asw, al);
#pragma unroll
            for (int q = 0; q < NT2; q++) {
                uint32_t bo = sw128((uint32_t)((16 * q + brow) * 128 + bseg * 16 + ks * 32));
                uint32_t bh[4], bl[4];
                ldsm4(Bh + bo, bh);
                ldsm4(Bl + bo, bl);
                mma16816(acc[2 * q], ah, bh[0], bh[1]);
                mma16816(acc[2 * q + 1], ah, bh[2], bh[3]);
                mma16816(acc[2 * q], ah, bl[0], bl[1]);
                mma16816(acc[2 * q + 1], ah, bl[2], bl[3]);
                mma16816(acc[2 * q], al, bh[0], bh[1]);
                mma16816(acc[2 * q + 1], al, bh[2], bh[3]);
            }
            if constexpr (NT & 1) {
                uint32_t bo = sw128((uint32_t)((8 * (NT - 1) + (lane & 7)) * 128 +
                                               ((lane >> 3) & 1) * 16 + ks * 32));
                uint32_t bh2[2], bl2[2];
                ldsm2(Bh + bo, bh2);
                ldsm2(Bl + bo, bl2);
                mma16816(acc[NT - 1], ah, bh2[0], bh2[1]);
                mma16816(acc[NT - 1], ah, bl2[0], bl2[1]);
                mma16816(acc[NT - 1], al, bh2[0], bh2[1]);
            }
        }
    };

    // ---------------- main pipeline ----------------
    float xb0[5], xb1[5];
    prefetch(0, xb0);
    if (NCHUNK > 1) prefetch(1, xb1);
    stageB(0, 0);
    scatter(0, 0, xb0);
    cp_wait0();
    __syncthreads();

    for (int c = 0; c < NCHUNK; c++) {
        const int st = c & 1;
        if (c + 2 < NCHUNK) prefetch(c + 2, (c & 1) ? xb1 : xb0);
        if (c + 1 < NCHUNK) stageB(c + 1, st ^ 1);
        mma_chunk(st);
        if (c + 1 < NCHUNK) scatter(c + 1, st ^ 1, ((c + 1) & 1) ? xb1 : xb0);
        cp_wait0();
        __syncthreads();
    }

    // ---------------- epilogue: smem transpose -> coalesced STG ----------------
    constexpr int SP = 132;
    float* S = reinterpret_cast<float*>(dsm);  // reuse A region
    {
        const int er0 = wid * 16 + (lane >> 2);
        const int er1 = er0 + 8;
#pragma unroll
        for (int p = 0; p < NT; p++) {
            int o = p * 8 + (lane & 3) * 2;
            S[o * SP + er0] = acc[p][0];
            S[(o + 1) * SP + er0] = acc[p][1];
            S[o * SP + er1] = acc[p][2];
            S[(o + 1) * SP + er1] = acc[p][3];
        }
    }
    __syncthreads();
    for (int idx = tid; idx < OUT * 128; idx += 256) {
        int o = idx >> 7;
        int rr = idx & 127;
        float val = S[o * SP + rr];
        if (OUT_NCHW) hout[((row0 >> 12) * OUT + o) * 4096 + (row0 & 4095) + rr] = val;
        else hout[o * N + row0 + rr] = val;
    }
}

// ------------------------------- launch ------------------------------------

extern "C" void kernel_launch(void* const* d_in, const int* in_sizes, int n_in,
                              void* d_out, int out_size) {
    const float* x     = (const float*)d_in[0];
    const float* grid0 = (const float*)d_in[1];
    const float* coef0 = (const float*)d_in[2];
    const float* sb0   = (const float*)d_in[3];
    const float* ss0   = (const float*)d_in[4];
    const float* grid1 = (const float*)d_in[5];
    const float* coef1 = (const float*)d_in[6];
    const float* sb1   = (const float*)d_in[7];
    const float* ss1   = (const float*)d_in[8];
    const float* grid2 = (const float*)d_in[9];
    const float* coef2 = (const float*)d_in[10];
    const float* sb2   = (const float*)d_in[11];
    const float* ss2   = (const float*)d_in[12];
    float* out = (float*)d_out;

    int N = in_sizes[0] / 12;
    if (N > MAXN) N = MAXN;

    float *h1, *h2;
    __nv_bfloat16 *Whi0, *Wlo0, *Whi1, *Wlo1, *Whi2, *Wlo2;
    cudaGetSymbolAddress((void**)&h1, g_h1);
    cudaGetSymbolAddress((void**)&h2, g_h2);
    cudaGetSymbolAddress((void**)&Whi0, g_Whi0);
    cudaGetSymbolAddress((void**)&Wlo0, g_Wlo0);
    cudaGetSymbolAddress((void**)&Whi1, g_Whi1);
    cudaGetSymbolAddress((void**)&Wlo1, g_Wlo1);
    cudaGetSymbolAddress((void**)&Whi2, g_Whi2);
    cudaGetSymbolAddress((void**)&Wlo2, g_Wlo2);

    fold_hilo<<<(64 * 128 + 255) / 256, 256>>>(coef0, sb0, ss0, Whi0, Wlo0, 12, 64, 128);
    fold_hilo<<<(64 * 576 + 255) / 256, 256>>>(coef1, sb1, ss1, Whi1, Wlo1, 64, 64, 576);
    fold_hilo<<<(24 * 576 + 255) / 256, 256>>>(coef2, sb2, ss2, Whi2, Wlo2, 64, 24, 576);

    auto k0 = kan_mma<12, 64, 108, 128, 2, true, false>;
    auto k1 = kan_mma<64, 64, 576, 576, 9, false, false>;
    auto k2 = kan_mma<64, 24, 576, 576, 9, false, true>;

    constexpr int SM01 = 4 * 128 * 128 + 4 * 64 * 128;  // 98304
    constexpr int SM2  = 4 * 128 * 128 + 4 * 24 * 128;  // 77824
    cudaFuncSetAttribute(k0, cudaFuncAttributeMaxDynamicSharedMemorySize, SM01);
    cudaFuncSetAttribute(k1, cudaFuncAttributeMaxDynamicSharedMemorySize, SM01);
    cudaFuncSetAttribute(k2, cudaFuncAttributeMaxDynamicSharedMemorySize, SM2);

    int blocks = N / 128;
    k0<<<blocks, 256, SM01>>>(x, grid0, Whi0, Wlo0, h1, N);
    k1<<<blocks, 256, SM01>>>(h1, grid1, Whi1, Wlo1, h2, N);
    k2<<<blocks, 256, SM2>>>(h2, grid2, Whi2, Wlo2, out, N);
}